// round 15
// baseline (speedup 1.0000x reference)
#include <cuda_runtime.h>
#include <cuda_bf16.h>
#include <math.h>

// Problem constants (fixed shapes)
#define BATCH 256
#define SEQT  512
#define DIN   512
#define HID   64
#define GATES 256           // 4*HID
#define MROWS (BATCH*SEQT)  // 131072

// Scratch (static device globals — allocation-free per harness rules)
__device__ float g_xproj[(size_t)MROWS * GATES];   // 128 MiB
__device__ float g_pooled[BATCH * HID];

// ---------------------------------------------------------------------------
// Kernel 1: x_proj[m,n] = sum_k x[m,k] * W_ih[n,k] + b_ih[n] + b_hh[n]
// 128x128 block tile, BK=8, 8x8 per-thread register tile, register prefetch.
// ---------------------------------------------------------------------------
__global__ __launch_bounds__(256) void gemm_xproj_kernel(
    const float* __restrict__ A,     // x   [MROWS, DIN]
    const float* __restrict__ Bw,    // W_ih [GATES, DIN]
    const float* __restrict__ b_ih,
    const float* __restrict__ b_hh,
    float* __restrict__ C)           // [MROWS, GATES]
{
    const int K = DIN;
    __shared__ __align__(16) float As[8][128];
    __shared__ __align__(16) float Bs[8][128];

    const int tid   = threadIdx.x;
    const int mBase = blockIdx.x * 128;
    const int nBase = blockIdx.y * 128;

    const int lrow = tid >> 1;        // 0..127
    const int lcol = (tid & 1) * 4;   // 0 or 4

    const float* Aptr = A  + (size_t)(mBase + lrow) * K + lcol;
    const float* Bptr = Bw + (size_t)(nBase + lrow) * K + lcol;

    const int tm = (tid >> 4) * 8;    // 0..120
    const int tn = (tid & 15) * 8;    // 0..120

    float acc[8][8];
    #pragma unroll
    for (int i = 0; i < 8; i++)
        #pragma unroll
        for (int j = 0; j < 8; j++) acc[i][j] = 0.f;

    float4 aReg = *reinterpret_cast<const float4*>(Aptr);
    float4 bReg = *reinterpret_cast<const float4*>(Bptr);

    for (int k0 = 0; k0 < K; k0 += 8) {
        // store staged tile (transposed: [k][m] / [k][n])
        As[lcol + 0][lrow] = aReg.x;
        As[lcol + 1][lrow] = aReg.y;
        As[lcol + 2][lrow] = aReg.z;
        As[lcol + 3][lrow] = aReg.w;
        Bs[lcol + 0][lrow] = bReg.x;
        Bs[lcol + 1][lrow] = bReg.y;
        Bs[lcol + 2][lrow] = bReg.z;
        Bs[lcol + 3][lrow] = bReg.w;
        __syncthreads();

        // prefetch next tile into registers
        if (k0 + 8 < K) {
            aReg = *reinterpret_cast<const float4*>(Aptr + k0 + 8);
            bReg = *reinterpret_cast<const float4*>(Bptr + k0 + 8);
        }

        #pragma unroll
        for (int kk = 0; kk < 8; kk++) {
            float4 a0 = *reinterpret_cast<const float4*>(&As[kk][tm]);
            float4 a1 = *reinterpret_cast<const float4*>(&As[kk][tm + 4]);
            float4 b0 = *reinterpret_cast<const float4*>(&Bs[kk][tn]);
            float4 b1 = *reinterpret_cast<const float4*>(&Bs[kk][tn + 4]);
            float af[8] = {a0.x, a0.y, a0.z, a0.w, a1.x, a1.y, a1.z, a1.w};
            float bf[8] = {b0.x, b0.y, b0.z, b0.w, b1.x, b1.y, b1.z, b1.w};
            #pragma unroll
            for (int i = 0; i < 8; i++)
                #pragma unroll
                for (int j = 0; j < 8; j++)
                    acc[i][j] += af[i] * bf[j];
        }
        __syncthreads();
    }

    // epilogue: add biases, store
    const int row0 = mBase + tm;
    const int col0 = nBase + tn;
    float bias[8];
    #pragma unroll
    for (int j = 0; j < 8; j++) bias[j] = b_ih[col0 + j] + b_hh[col0 + j];

    #pragma unroll
    for (int i = 0; i < 8; i++) {
        float4 v0, v1;
        v0.x = acc[i][0] + bias[0];
        v0.y = acc[i][1] + bias[1];
        v0.z = acc[i][2] + bias[2];
        v0.w = acc[i][3] + bias[3];
        v1.x = acc[i][4] + bias[4];
        v1.y = acc[i][5] + bias[5];
        v1.z = acc[i][6] + bias[6];
        v1.w = acc[i][7] + bias[7];
        float* Cp = C + (size_t)(row0 + i) * GATES + col0;
        *reinterpret_cast<float4*>(Cp)     = v0;
        *reinterpret_cast<float4*>(Cp + 4) = v1;
    }
}

// ---------------------------------------------------------------------------
// Kernel 2: sequential LSTM scan, one block per batch element.
// Thread g owns W_hh row g in registers; h broadcast through shared memory.
// Accumulates mean-pooled h on the fly.
// ---------------------------------------------------------------------------
__device__ __forceinline__ float sigmoid_f(float x) {
    return 1.0f / (1.0f + __expf(-x));
}

__global__ __launch_bounds__(256) void lstm_scan_kernel(
    const float* __restrict__ xproj,   // [BATCH*SEQT, GATES]
    const float* __restrict__ W_hh,    // [GATES, HID]
    float* __restrict__ pooled)        // [BATCH, HID]
{
    __shared__ __align__(16) float h_sh[HID];
    __shared__ float gates_sh[GATES];

    const int tid = threadIdx.x;       // gate row 0..255
    const int b   = blockIdx.x;

    // Load this thread's W_hh row into registers (16 x float4 = 64 floats)
    float4 wr[16];
    const float4* w4 = reinterpret_cast<const float4*>(W_hh + tid * HID);
    #pragma unroll
    for (int i = 0; i < 16; i++) wr[i] = w4[i];

    if (tid < HID) h_sh[tid] = 0.f;

    float c = 0.f;
    float hsum = 0.f;

    const float* xp = xproj + (size_t)b * SEQT * GATES;
    float xv = xp[tid];   // t = 0 preactivation (biases already folded in)
    __syncthreads();

    for (int t = 0; t < SEQT; t++) {
        // prefetch next timestep's input projection (hides LDG latency)
        float xnext = (t < SEQT - 1) ? xp[(size_t)(t + 1) * GATES + tid] : 0.f;

        // gates[tid] = xv + dot(W_hh[tid,:], h_prev)
        float acc0 = xv, acc1 = 0.f;
        const float4* h4 = reinterpret_cast<const float4*>(h_sh);
        #pragma unroll
        for (int i = 0; i < 16; i += 2) {
            float4 hv0 = h4[i];
            float4 hv1 = h4[i + 1];
            acc0 += wr[i].x * hv0.x + wr[i].y * hv0.y +
                    wr[i].z * hv0.z + wr[i].w * hv0.w;
            acc1 += wr[i + 1].x * hv1.x + wr[i + 1].y * hv1.y +
                    wr[i + 1].z * hv1.z + wr[i + 1].w * hv1.w;
        }
        gates_sh[tid] = acc0 + acc1;
        __syncthreads();

        if (tid < HID) {
            float ig = sigmoid_f(gates_sh[tid]);
            float fg = sigmoid_f(gates_sh[HID + tid]);
            float gg = tanhf(gates_sh[2 * HID + tid]);
            float og = sigmoid_f(gates_sh[3 * HID + tid]);
            c = fg * c + ig * gg;
            float h = og * tanhf(c);
            hsum += h;
            h_sh[tid] = h;
        }
        __syncthreads();
        xv = xnext;
    }

    if (tid < HID) pooled[b * HID + tid] = hsum * (1.0f / (float)SEQT);
}

// ---------------------------------------------------------------------------
// Kernel 3: MLP head + softmax. Warp per batch element (8 warps/block).
// ---------------------------------------------------------------------------
__global__ __launch_bounds__(256) void mlp_head_kernel(
    const float* __restrict__ pooled,  // [BATCH, HID]
    const float* __restrict__ W1,      // [32, 64]
    const float* __restrict__ b1,      // [32]
    const float* __restrict__ W2,      // [3, 32]
    const float* __restrict__ b2,      // [3]
    float* __restrict__ out)           // [BATCH, 3]
{
    __shared__ float w1s[32][65];      // padded to kill bank conflicts
    __shared__ float ps[8][64];

    const int tid  = threadIdx.x;
    const int warp = tid >> 5;
    const int lane = tid & 31;
    const int b    = blockIdx.x * 8 + warp;

    // stage W1 into shared (32*64 = 2048 floats)
    for (int i = tid; i < 32 * 64; i += 256)
        w1s[i >> 6][i & 63] = W1[i];

    // stage pooled vector for this warp's batch
    ps[warp][lane]      = pooled[b * HID + lane];
    ps[warp][lane + 32] = pooled[b * HID + lane + 32];
    __syncthreads();

    // hidden layer: lane j computes h1[j] = relu(b1[j] + W1[j,:] . pooled)
    float acc = b1[lane];
    #pragma unroll
    for (int k = 0; k < 64; k++)
        acc += w1s[lane][k] * ps[warp][k];
    float h1 = fmaxf(acc, 0.f);

    // output layer: 3 logits via warp shuffle reductions
    float lg[3];
    #pragma unroll
    for (int k = 0; k < 3; k++) {
        float v = h1 * W2[k * 32 + lane];
        #pragma unroll
        for (int off = 16; off; off >>= 1)
            v += __shfl_xor_sync(0xffffffffu, v, off);
        lg[k] = v + b2[k];
    }

    if (lane == 0) {
        float m  = fmaxf(lg[0], fmaxf(lg[1], lg[2]));
        float e0 = expf(lg[0] - m);
        float e1 = expf(lg[1] - m);
        float e2 = expf(lg[2] - m);
        float inv = 1.0f / (e0 + e1 + e2);
        out[b * 3 + 0] = e0 * inv;
        out[b * 3 + 1] = e1 * inv;
        out[b * 3 + 2] = e2 * inv;
    }
}

// ---------------------------------------------------------------------------
extern "C" void kernel_launch(void* const* d_in, const int* in_sizes, int n_in,
                              void* d_out, int out_size) {
    const float* x    = (const float*)d_in[0];
    const float* W_ih = (const float*)d_in[1];
    const float* W_hh = (const float*)d_in[2];
    const float* b_ih = (const float*)d_in[3];
    const float* b_hh = (const float*)d_in[4];
    const float* W1   = (const float*)d_in[5];
    const float* b1   = (const float*)d_in[6];
    const float* W2   = (const float*)d_in[7];
    const float* b2   = (const float*)d_in[8];
    float* out = (float*)d_out;

    float* xproj;
    float* pooled;
    cudaGetSymbolAddress((void**)&xproj,  g_xproj);
    cudaGetSymbolAddress((void**)&pooled, g_pooled);

    dim3 ggrid(MROWS / 128, GATES / 128);
    gemm_xproj_kernel<<<ggrid, 256>>>(x, W_ih, b_ih, b_hh, xproj);
    lstm_scan_kernel<<<BATCH, 256>>>(xproj, W_hh, pooled);
    mlp_head_kernel<<<BATCH / 8, 256>>>(pooled, W1, b1, W2, b2, out);
}

// round 16
// speedup vs baseline: 1.0038x; 1.0038x over previous
#include <cuda_runtime.h>
#include <cuda_bf16.h>
#include <math.h>

// Problem constants (fixed shapes)
#define BATCH 256
#define SEQT  512
#define DIN   512
#define HID   64
#define GATES 256           // 4*HID
#define MROWS (BATCH*SEQT)  // 131072

// Scratch (static device globals — allocation-free per harness rules)
__device__ float g_xproj[(size_t)MROWS * GATES];   // 128 MiB
__device__ float g_pooled[BATCH * HID];

// ---------------------------------------------------------------------------
// Kernel 1: x_proj[m,n] = sum_k x[m,k] * W_ih[n,k] + b_ih[n] + b_hh[n]
// 128x128 block tile, BK=8, 8x8 per-thread register tile, register prefetch.
// ---------------------------------------------------------------------------
__global__ __launch_bounds__(256) void gemm_xproj_kernel(
    const float* __restrict__ A,     // x   [MROWS, DIN]
    const float* __restrict__ Bw,    // W_ih [GATES, DIN]
    const float* __restrict__ b_ih,
    const float* __restrict__ b_hh,
    float* __restrict__ C)           // [MROWS, GATES]
{
    const int K = DIN;
    __shared__ __align__(16) float As[8][128];
    __shared__ __align__(16) float Bs[8][128];

    const int tid   = threadIdx.x;
    const int mBase = blockIdx.x * 128;
    const int nBase = blockIdx.y * 128;

    const int lrow = tid >> 1;        // 0..127
    const int lcol = (tid & 1) * 4;   // 0 or 4

    const float* Aptr = A  + (size_t)(mBase + lrow) * K + lcol;
    const float* Bptr = Bw + (size_t)(nBase + lrow) * K + lcol;

    const int tm = (tid >> 4) * 8;    // 0..120
    const int tn = (tid & 15) * 8;    // 0..120

    float acc[8][8];
    #pragma unroll
    for (int i = 0; i < 8; i++)
        #pragma unroll
        for (int j = 0; j < 8; j++) acc[i][j] = 0.f;

    float4 aReg = *reinterpret_cast<const float4*>(Aptr);
    float4 bReg = *reinterpret_cast<const float4*>(Bptr);

    for (int k0 = 0; k0 < K; k0 += 8) {
        // store staged tile (transposed: [k][m] / [k][n])
        As[lcol + 0][lrow] = aReg.x;
        As[lcol + 1][lrow] = aReg.y;
        As[lcol + 2][lrow] = aReg.z;
        As[lcol + 3][lrow] = aReg.w;
        Bs[lcol + 0][lrow] = bReg.x;
        Bs[lcol + 1][lrow] = bReg.y;
        Bs[lcol + 2][lrow] = bReg.z;
        Bs[lcol + 3][lrow] = bReg.w;
        __syncthreads();

        // prefetch next tile into registers
        if (k0 + 8 < K) {
            aReg = *reinterpret_cast<const float4*>(Aptr + k0 + 8);
            bReg = *reinterpret_cast<const float4*>(Bptr + k0 + 8);
        }

        #pragma unroll
        for (int kk = 0; kk < 8; kk++) {
            float4 a0 = *reinterpret_cast<const float4*>(&As[kk][tm]);
            float4 a1 = *reinterpret_cast<const float4*>(&As[kk][tm + 4]);
            float4 b0 = *reinterpret_cast<const float4*>(&Bs[kk][tn]);
            float4 b1 = *reinterpret_cast<const float4*>(&Bs[kk][tn + 4]);
            float af[8] = {a0.x, a0.y, a0.z, a0.w, a1.x, a1.y, a1.z, a1.w};
            float bf[8] = {b0.x, b0.y, b0.z, b0.w, b1.x, b1.y, b1.z, b1.w};
            #pragma unroll
            for (int i = 0; i < 8; i++)
                #pragma unroll
                for (int j = 0; j < 8; j++)
                    acc[i][j] += af[i] * bf[j];
        }
        __syncthreads();
    }

    // epilogue: add biases, store
    const int row0 = mBase + tm;
    const int col0 = nBase + tn;
    float bias[8];
    #pragma unroll
    for (int j = 0; j < 8; j++) bias[j] = b_ih[col0 + j] + b_hh[col0 + j];

    #pragma unroll
    for (int i = 0; i < 8; i++) {
        float4 v0, v1;
        v0.x = acc[i][0] + bias[0];
        v0.y = acc[i][1] + bias[1];
        v0.z = acc[i][2] + bias[2];
        v0.w = acc[i][3] + bias[3];
        v1.x = acc[i][4] + bias[4];
        v1.y = acc[i][5] + bias[5];
        v1.z = acc[i][6] + bias[6];
        v1.w = acc[i][7] + bias[7];
        float* Cp = C + (size_t)(row0 + i) * GATES + col0;
        *reinterpret_cast<float4*>(Cp)     = v0;
        *reinterpret_cast<float4*>(Cp + 4) = v1;
    }
}

// ---------------------------------------------------------------------------
// Kernel 2: sequential LSTM scan, one block per batch element.
// Thread g owns W_hh row g in registers; h broadcast through shared memory.
// Accumulates mean-pooled h on the fly.
// ---------------------------------------------------------------------------
__device__ __forceinline__ float sigmoid_f(float x) {
    return 1.0f / (1.0f + __expf(-x));
}

__global__ __launch_bounds__(256) void lstm_scan_kernel(
    const float* __restrict__ xproj,   // [BATCH*SEQT, GATES]
    const float* __restrict__ W_hh,    // [GATES, HID]
    float* __restrict__ pooled)        // [BATCH, HID]
{
    __shared__ __align__(16) float h_sh[HID];
    __shared__ float gates_sh[GATES];

    const int tid = threadIdx.x;       // gate row 0..255
    const int b   = blockIdx.x;

    // Load this thread's W_hh row into registers (16 x float4 = 64 floats)
    float4 wr[16];
    const float4* w4 = reinterpret_cast<const float4*>(W_hh + tid * HID);
    #pragma unroll
    for (int i = 0; i < 16; i++) wr[i] = w4[i];

    if (tid < HID) h_sh[tid] = 0.f;

    float c = 0.f;
    float hsum = 0.f;

    const float* xp = xproj + (size_t)b * SEQT * GATES;
    float xv = xp[tid];   // t = 0 preactivation (biases already folded in)
    __syncthreads();

    for (int t = 0; t < SEQT; t++) {
        // prefetch next timestep's input projection (hides LDG latency)
        float xnext = (t < SEQT - 1) ? xp[(size_t)(t + 1) * GATES + tid] : 0.f;

        // gates[tid] = xv + dot(W_hh[tid,:], h_prev)
        float acc0 = xv, acc1 = 0.f;
        const float4* h4 = reinterpret_cast<const float4*>(h_sh);
        #pragma unroll
        for (int i = 0; i < 16; i += 2) {
            float4 hv0 = h4[i];
            float4 hv1 = h4[i + 1];
            acc0 += wr[i].x * hv0.x + wr[i].y * hv0.y +
                    wr[i].z * hv0.z + wr[i].w * hv0.w;
            acc1 += wr[i + 1].x * hv1.x + wr[i + 1].y * hv1.y +
                    wr[i + 1].z * hv1.z + wr[i + 1].w * hv1.w;
        }
        gates_sh[tid] = acc0 + acc1;
        __syncthreads();

        if (tid < HID) {
            float ig = sigmoid_f(gates_sh[tid]);
            float fg = sigmoid_f(gates_sh[HID + tid]);
            float gg = tanhf(gates_sh[2 * HID + tid]);
            float og = sigmoid_f(gates_sh[3 * HID + tid]);
            c = fg * c + ig * gg;
            float h = og * tanhf(c);
            hsum += h;
            h_sh[tid] = h;
        }
        __syncthreads();
        xv = xnext;
    }

    if (tid < HID) pooled[b * HID + tid] = hsum * (1.0f / (float)SEQT);
}

// ---------------------------------------------------------------------------
// Kernel 3: MLP head + softmax. Warp per batch element (8 warps/block).
// ---------------------------------------------------------------------------
__global__ __launch_bounds__(256) void mlp_head_kernel(
    const float* __restrict__ pooled,  // [BATCH, HID]
    const float* __restrict__ W1,      // [32, 64]
    const float* __restrict__ b1,      // [32]
    const float* __restrict__ W2,      // [3, 32]
    const float* __restrict__ b2,      // [3]
    float* __restrict__ out)           // [BATCH, 3]
{
    __shared__ float w1s[32][65];      // padded to kill bank conflicts
    __shared__ float ps[8][64];

    const int tid  = threadIdx.x;
    const int warp = tid >> 5;
    const int lane = tid & 31;
    const int b    = blockIdx.x * 8 + warp;

    // stage W1 into shared (32*64 = 2048 floats)
    for (int i = tid; i < 32 * 64; i += 256)
        w1s[i >> 6][i & 63] = W1[i];

    // stage pooled vector for this warp's batch
    ps[warp][lane]      = pooled[b * HID + lane];
    ps[warp][lane + 32] = pooled[b * HID + lane + 32];
    __syncthreads();

    // hidden layer: lane j computes h1[j] = relu(b1[j] + W1[j,:] . pooled)
    float acc = b1[lane];
    #pragma unroll
    for (int k = 0; k < 64; k++)
        acc += w1s[lane][k] * ps[warp][k];
    float h1 = fmaxf(acc, 0.f);

    // output layer: 3 logits via warp shuffle reductions
    float lg[3];
    #pragma unroll
    for (int k = 0; k < 3; k++) {
        float v = h1 * W2[k * 32 + lane];
        #pragma unroll
        for (int off = 16; off; off >>= 1)
            v += __shfl_xor_sync(0xffffffffu, v, off);
        lg[k] = v + b2[k];
    }

    if (lane == 0) {
        float m  = fmaxf(lg[0], fmaxf(lg[1], lg[2]));
        float e0 = expf(lg[0] - m);
        float e1 = expf(lg[1] - m);
        float e2 = expf(lg[2] - m);
        float inv = 1.0f / (e0 + e1 + e2);
        out[b * 3 + 0] = e0 * inv;
        out[b * 3 + 1] = e1 * inv;
        out[b * 3 + 2] = e2 * inv;
    }
}

// ---------------------------------------------------------------------------
extern "C" void kernel_launch(void* const* d_in, const int* in_sizes, int n_in,
                              void* d_out, int out_size) {
    const float* x    = (const float*)d_in[0];
    const float* W_ih = (const float*)d_in[1];
    const float* W_hh = (const float*)d_in[2];
    const float* b_ih = (const float*)d_in[3];
    const float* b_hh = (const float*)d_in[4];
    const float* W1   = (const float*)d_in[5];
    const float* b1   = (const float*)d_in[6];
    const float* W2   = (const float*)d_in[7];
    const float* b2   = (const float*)d_in[8];
    float* out = (float*)d_out;

    float* xproj;
    float* pooled;
    cudaGetSymbolAddress((void**)&xproj,  g_xproj);
    cudaGetSymbolAddress((void**)&pooled, g_pooled);

    dim3 ggrid(MROWS / 128, GATES / 128);
    gemm_xproj_kernel<<<ggrid, 256>>>(x, W_ih, b_ih, b_hh, xproj);
    lstm_scan_kernel<<<BATCH, 256>>>(xproj, W_hh, pooled);
    mlp_head_kernel<<<BATCH / 8, 256>>>(pooled, W1, b1, W2, b2, out);
}

// round 17
// speedup vs baseline: 1.0041x; 1.0003x over previous
#include <cuda_runtime.h>
#include <cuda_bf16.h>
#include <math.h>

// Problem constants (fixed shapes)
#define BATCH 256
#define SEQT  512
#define DIN   512
#define HID   64
#define GATES 256           // 4*HID
#define MROWS (BATCH*SEQT)  // 131072

// Scratch (static device globals — allocation-free per harness rules)
__device__ float g_xproj[(size_t)MROWS * GATES];   // 128 MiB
__device__ float g_pooled[BATCH * HID];

// ---------------------------------------------------------------------------
// Kernel 1: x_proj[m,n] = sum_k x[m,k] * W_ih[n,k] + b_ih[n] + b_hh[n]
// 128x128 block tile, BK=8, 8x8 per-thread register tile, register prefetch.
// ---------------------------------------------------------------------------
__global__ __launch_bounds__(256) void gemm_xproj_kernel(
    const float* __restrict__ A,     // x   [MROWS, DIN]
    const float* __restrict__ Bw,    // W_ih [GATES, DIN]
    const float* __restrict__ b_ih,
    const float* __restrict__ b_hh,
    float* __restrict__ C)           // [MROWS, GATES]
{
    const int K = DIN;
    __shared__ __align__(16) float As[8][128];
    __shared__ __align__(16) float Bs[8][128];

    const int tid   = threadIdx.x;
    const int mBase = blockIdx.x * 128;
    const int nBase = blockIdx.y * 128;

    const int lrow = tid >> 1;        // 0..127
    const int lcol = (tid & 1) * 4;   // 0 or 4

    const float* Aptr = A  + (size_t)(mBase + lrow) * K + lcol;
    const float* Bptr = Bw + (size_t)(nBase + lrow) * K + lcol;

    const int tm = (tid >> 4) * 8;    // 0..120
    const int tn = (tid & 15) * 8;    // 0..120

    float acc[8][8];
    #pragma unroll
    for (int i = 0; i < 8; i++)
        #pragma unroll
        for (int j = 0; j < 8; j++) acc[i][j] = 0.f;

    float4 aReg = *reinterpret_cast<const float4*>(Aptr);
    float4 bReg = *reinterpret_cast<const float4*>(Bptr);

    for (int k0 = 0; k0 < K; k0 += 8) {
        // store staged tile (transposed: [k][m] / [k][n])
        As[lcol + 0][lrow] = aReg.x;
        As[lcol + 1][lrow] = aReg.y;
        As[lcol + 2][lrow] = aReg.z;
        As[lcol + 3][lrow] = aReg.w;
        Bs[lcol + 0][lrow] = bReg.x;
        Bs[lcol + 1][lrow] = bReg.y;
        Bs[lcol + 2][lrow] = bReg.z;
        Bs[lcol + 3][lrow] = bReg.w;
        __syncthreads();

        // prefetch next tile into registers
        if (k0 + 8 < K) {
            aReg = *reinterpret_cast<const float4*>(Aptr + k0 + 8);
            bReg = *reinterpret_cast<const float4*>(Bptr + k0 + 8);
        }

        #pragma unroll
        for (int kk = 0; kk < 8; kk++) {
            float4 a0 = *reinterpret_cast<const float4*>(&As[kk][tm]);
            float4 a1 = *reinterpret_cast<const float4*>(&As[kk][tm + 4]);
            float4 b0 = *reinterpret_cast<const float4*>(&Bs[kk][tn]);
            float4 b1 = *reinterpret_cast<const float4*>(&Bs[kk][tn + 4]);
            float af[8] = {a0.x, a0.y, a0.z, a0.w, a1.x, a1.y, a1.z, a1.w};
            float bf[8] = {b0.x, b0.y, b0.z, b0.w, b1.x, b1.y, b1.z, b1.w};
            #pragma unroll
            for (int i = 0; i < 8; i++)
                #pragma unroll
                for (int j = 0; j < 8; j++)
                    acc[i][j] += af[i] * bf[j];
        }
        __syncthreads();
    }

    // epilogue: add biases, store
    const int row0 = mBase + tm;
    const int col0 = nBase + tn;
    float bias[8];
    #pragma unroll
    for (int j = 0; j < 8; j++) bias[j] = b_ih[col0 + j] + b_hh[col0 + j];

    #pragma unroll
    for (int i = 0; i < 8; i++) {
        float4 v0, v1;
        v0.x = acc[i][0] + bias[0];
        v0.y = acc[i][1] + bias[1];
        v0.z = acc[i][2] + bias[2];
        v0.w = acc[i][3] + bias[3];
        v1.x = acc[i][4] + bias[4];
        v1.y = acc[i][5] + bias[5];
        v1.z = acc[i][6] + bias[6];
        v1.w = acc[i][7] + bias[7];
        float* Cp = C + (size_t)(row0 + i) * GATES + col0;
        *reinterpret_cast<float4*>(Cp)     = v0;
        *reinterpret_cast<float4*>(Cp + 4) = v1;
    }
}

// ---------------------------------------------------------------------------
// Kernel 2: sequential LSTM scan, one block per batch element.
// Thread g owns W_hh row g in registers; h broadcast through shared memory.
// Accumulates mean-pooled h on the fly.
// ---------------------------------------------------------------------------
__device__ __forceinline__ float sigmoid_f(float x) {
    return 1.0f / (1.0f + __expf(-x));
}

__global__ __launch_bounds__(256) void lstm_scan_kernel(
    const float* __restrict__ xproj,   // [BATCH*SEQT, GATES]
    const float* __restrict__ W_hh,    // [GATES, HID]
    float* __restrict__ pooled)        // [BATCH, HID]
{
    __shared__ __align__(16) float h_sh[HID];
    __shared__ float gates_sh[GATES];

    const int tid = threadIdx.x;       // gate row 0..255
    const int b   = blockIdx.x;

    // Load this thread's W_hh row into registers (16 x float4 = 64 floats)
    float4 wr[16];
    const float4* w4 = reinterpret_cast<const float4*>(W_hh + tid * HID);
    #pragma unroll
    for (int i = 0; i < 16; i++) wr[i] = w4[i];

    if (tid < HID) h_sh[tid] = 0.f;

    float c = 0.f;
    float hsum = 0.f;

    const float* xp = xproj + (size_t)b * SEQT * GATES;
    float xv = xp[tid];   // t = 0 preactivation (biases already folded in)
    __syncthreads();

    for (int t = 0; t < SEQT; t++) {
        // prefetch next timestep's input projection (hides LDG latency)
        float xnext = (t < SEQT - 1) ? xp[(size_t)(t + 1) * GATES + tid] : 0.f;

        // gates[tid] = xv + dot(W_hh[tid,:], h_prev)
        float acc0 = xv, acc1 = 0.f;
        const float4* h4 = reinterpret_cast<const float4*>(h_sh);
        #pragma unroll
        for (int i = 0; i < 16; i += 2) {
            float4 hv0 = h4[i];
            float4 hv1 = h4[i + 1];
            acc0 += wr[i].x * hv0.x + wr[i].y * hv0.y +
                    wr[i].z * hv0.z + wr[i].w * hv0.w;
            acc1 += wr[i + 1].x * hv1.x + wr[i + 1].y * hv1.y +
                    wr[i + 1].z * hv1.z + wr[i + 1].w * hv1.w;
        }
        gates_sh[tid] = acc0 + acc1;
        __syncthreads();

        if (tid < HID) {
            float ig = sigmoid_f(gates_sh[tid]);
            float fg = sigmoid_f(gates_sh[HID + tid]);
            float gg = tanhf(gates_sh[2 * HID + tid]);
            float og = sigmoid_f(gates_sh[3 * HID + tid]);
            c = fg * c + ig * gg;
            float h = og * tanhf(c);
            hsum += h;
            h_sh[tid] = h;
        }
        __syncthreads();
        xv = xnext;
    }

    if (tid < HID) pooled[b * HID + tid] = hsum * (1.0f / (float)SEQT);
}

// ---------------------------------------------------------------------------
// Kernel 3: MLP head + softmax. Warp per batch element (8 warps/block).
// ---------------------------------------------------------------------------
__global__ __launch_bounds__(256) void mlp_head_kernel(
    const float* __restrict__ pooled,  // [BATCH, HID]
    const float* __restrict__ W1,      // [32, 64]
    const float* __restrict__ b1,      // [32]
    const float* __restrict__ W2,      // [3, 32]
    const float* __restrict__ b2,      // [3]
    float* __restrict__ out)           // [BATCH, 3]
{
    __shared__ float w1s[32][65];      // padded to kill bank conflicts
    __shared__ float ps[8][64];

    const int tid  = threadIdx.x;
    const int warp = tid >> 5;
    const int lane = tid & 31;
    const int b    = blockIdx.x * 8 + warp;

    // stage W1 into shared (32*64 = 2048 floats)
    for (int i = tid; i < 32 * 64; i += 256)
        w1s[i >> 6][i & 63] = W1[i];

    // stage pooled vector for this warp's batch
    ps[warp][lane]      = pooled[b * HID + lane];
    ps[warp][lane + 32] = pooled[b * HID + lane + 32];
    __syncthreads();

    // hidden layer: lane j computes h1[j] = relu(b1[j] + W1[j,:] . pooled)
    float acc = b1[lane];
    #pragma unroll
    for (int k = 0; k < 64; k++)
        acc += w1s[lane][k] * ps[warp][k];
    float h1 = fmaxf(acc, 0.f);

    // output layer: 3 logits via warp shuffle reductions
    float lg[3];
    #pragma unroll
    for (int k = 0; k < 3; k++) {
        float v = h1 * W2[k * 32 + lane];
        #pragma unroll
        for (int off = 16; off; off >>= 1)
            v += __shfl_xor_sync(0xffffffffu, v, off);
        lg[k] = v + b2[k];
    }

    if (lane == 0) {
        float m  = fmaxf(lg[0], fmaxf(lg[1], lg[2]));
        float e0 = expf(lg[0] - m);
        float e1 = expf(lg[1] - m);
        float e2 = expf(lg[2] - m);
        float inv = 1.0f / (e0 + e1 + e2);
        out[b * 3 + 0] = e0 * inv;
        out[b * 3 + 1] = e1 * inv;
        out[b * 3 + 2] = e2 * inv;
    }
}

// ---------------------------------------------------------------------------
extern "C" void kernel_launch(void* const* d_in, const int* in_sizes, int n_in,
                              void* d_out, int out_size) {
    const float* x    = (const float*)d_in[0];
    const float* W_ih = (const float*)d_in[1];
    const float* W_hh = (const float*)d_in[2];
    const float* b_ih = (const float*)d_in[3];
    const float* b_hh = (const float*)d_in[4];
    const float* W1   = (const float*)d_in[5];
    const float* b1   = (const float*)d_in[6];
    const float* W2   = (const float*)d_in[7];
    const float* b2   = (const float*)d_in[8];
    float* out = (float*)d_out;

    float* xproj;
    float* pooled;
    cudaGetSymbolAddress((void**)&xproj,  g_xproj);
    cudaGetSymbolAddress((void**)&pooled, g_pooled);

    dim3 ggrid(MROWS / 128, GATES / 128);
    gemm_xproj_kernel<<<ggrid, 256>>>(x, W_ih, b_ih, b_hh, xproj);
    lstm_scan_kernel<<<BATCH, 256>>>(xproj, W_hh, pooled);
    mlp_head_kernel<<<BATCH / 8, 256>>>(pooled, W1, b1, W2, b2, out);
}